// round 17
// baseline (speedup 1.0000x reference)
#include <cuda_runtime.h>
#include <cuda_bf16.h>
#include <cstdint>

// ---------------------------------------------------------------------------
// Child-Sum Tree-LSTM, complete 4-ary tree depth 7.
// N_NODES=21845, N_INTERNAL=5461, HID=IN=512.
// Children of level-l rows [s,e) are exactly rows [4s+1, 4e+1) (level l+1).
//
// GEMMs: tensor cores (mma.sync.m16n8k16.bf16 — tcgen05 is NOT available in
// this toolchain: harness PTX targets sm_103 without 'a') with SPLIT-BF16
// 3-term fp32 emulation packed along K:
//   A'=[Ahi|Ahi|Alo], B'=[Bhi|Blo|Bhi], K'=1536,
//   C = Ahi.Bhi + Ahi.Blo + Alo.Bhi   (error ~2^-17, fp32 accumulate).
// R17: warp tile 64x32 -> 64x64 (4 warps/CTA): halves LDSM+issue overhead
// per HMMA. Big GEMM moved to 5th launch so ncu captures it.
// ---------------------------------------------------------------------------

#define N_NODES    21845
#define N_INTERNAL 5461
#define HID        512
#define KP         1536          // packed K' = 3*512

// fp32 scratch
__device__ float g_wx[N_INTERNAL * 2048];      // ~44.7 MB
__device__ float g_iou[1024 * 1536];           // 6 MB
__device__ float g_f[4096 * 512];              // 8 MB
__device__ float g_bias[2048];

// bf16 split operands
__device__ __nv_bfloat16 g_xb [N_INTERNAL * KP];
__device__ __nv_bfloat16 g_Wb [2048 * KP];
__device__ __nv_bfloat16 g_Uib[1536 * KP];
__device__ __nv_bfloat16 g_Ufb[ 512 * KP];
__device__ __nv_bfloat16 g_hsb[1024 * KP];
__device__ __nv_bfloat16 g_hlb[4096 * KP];

__device__ __forceinline__ float fast_tanh(float x) {
    float r;
    asm("tanh.approx.f32 %0, %1;" : "=f"(r) : "f"(x));
    return r;
}
__device__ __forceinline__ float fast_sigm(float x) {
    return 0.5f + 0.5f * fast_tanh(0.5f * x);
}
__device__ __forceinline__ void split_bf16(float v, __nv_bfloat16& hi, __nv_bfloat16& lo) {
    hi = __float2bfloat16_rn(v);
    lo = __float2bfloat16_rn(v - __bfloat162float(hi));
}

// ---------------------------------------------------------------------------
__global__ void zero_leaves_kernel(float4* __restrict__ h4, float4* __restrict__ c4)
{
    const int cnt = (N_NODES - N_INTERNAL) * HID / 4;
    int i = blockIdx.x * blockDim.x + threadIdx.x;
    if (i < cnt) {
        float4 z = make_float4(0.f, 0.f, 0.f, 0.f);
        h4[i] = z;
        c4[i] = z;
    }
}

__global__ void conv_x_kernel(const float* __restrict__ x)
{
    int i = blockIdx.x * blockDim.x + threadIdx.x;
    if (i >= N_INTERNAL * 512) return;
    int m = i >> 9, k = i & 511;
    __nv_bfloat16 hi, lo;
    split_bf16(x[(size_t)m * 512 + k], hi, lo);
    __nv_bfloat16* d = g_xb + (size_t)m * KP;
    d[k] = hi; d[512 + k] = hi; d[1024 + k] = lo;
}

__global__ void conv_w_kernel(const float* __restrict__ W_iou, const float* __restrict__ W_f,
                              const float* __restrict__ b_iou, const float* __restrict__ b_f)
{
    int i = blockIdx.x * blockDim.x + threadIdx.x;
    if (i < 2048) g_bias[i] = (i < 1536) ? b_iou[i] : b_f[i - 1536];
    if (i >= 2048 * 512) return;
    int n = i >> 9, k = i & 511;
    float v = (n < 1536) ? W_iou[(size_t)n * 512 + k] : W_f[(size_t)(n - 1536) * 512 + k];
    __nv_bfloat16 hi, lo;
    split_bf16(v, hi, lo);
    __nv_bfloat16* d = g_Wb + (size_t)n * KP;
    d[k] = hi; d[512 + k] = lo; d[1024 + k] = hi;
}

__global__ void conv_u_kernel(const float* __restrict__ U, __nv_bfloat16* __restrict__ dst, int rows)
{
    int i = blockIdx.x * blockDim.x + threadIdx.x;
    if (i >= rows * 512) return;
    int n = i >> 9, k = i & 511;
    __nv_bfloat16 hi, lo;
    split_bf16(U[(size_t)n * 512 + k], hi, lo);
    __nv_bfloat16* d = dst + (size_t)n * KP;
    d[k] = hi; d[512 + k] = lo; d[1024 + k] = hi;
}

__global__ void hsum_conv_kernel(const float* __restrict__ hlev, int M)
{
    int i = blockIdx.x * blockDim.x + threadIdx.x;
    if (i >= M * 512) return;
    int m = i >> 9, k = i & 511;
    const float* p = hlev + (size_t)m * 2048 + k;
    float s = p[0] + p[512] + p[1024] + p[1536];
    __nv_bfloat16 hi, lo;
    split_bf16(s, hi, lo);
    __nv_bfloat16* d = g_hsb + (size_t)m * KP;
    d[k] = hi; d[512 + k] = hi; d[1024 + k] = lo;
}

// ---------------------------------------------------------------------------
// bf16 tensor-core GEMM (NT): C[M,N] = A'[M,KP] * B'[N,KP]^T (+ col bias)
// CTA 128x128, BK=32, 4 warps (2x2), warp tile 64x64 = 4x8 m16n8k16.
// 3-stage cp.async ring (one __syncthreads per iter); ldmatrix.x4 fragments;
// smem rows padded to 20 u32 (80B) -> conflict-free LDSM & cp.async stores.
// Requires N % 128 == 0; M guarded via cp.async src-size zero-fill.
// ---------------------------------------------------------------------------
#define RSTR 20    // u32 per smem row (16 data + 4 pad)

__device__ __forceinline__ void cp16(uint32_t dst, const void* src, int pbytes) {
    asm volatile("cp.async.cg.shared.global [%0], [%1], 16, %2;"
                 :: "r"(dst), "l"(src), "r"(pbytes));
}

__global__ __launch_bounds__(128)
void gemm_bf16_3x(const __nv_bfloat16* __restrict__ A,
                  const __nv_bfloat16* __restrict__ B,
                  float* __restrict__ C, int ldc,
                  const float* __restrict__ bias,
                  int M, int N)
{
    __shared__ __align__(16) uint32_t SA[3][128][RSTR];
    __shared__ __align__(16) uint32_t SB[3][128][RSTR];

    const int t    = threadIdx.x;           // 0..127
    const int lane = t & 31;
    const int warp = t >> 5;                // 0..3
    const int g    = lane >> 2;
    const int tg   = lane & 3;
    const int wm   = warp >> 1;             // 0..1 (M dir, 64 rows)
    const int wn   = warp & 1;              // 0..1 (N dir, 64 cols)
    const int bm   = blockIdx.y * 128;
    const int bn   = blockIdx.x * 128;

    const uint32_t sa0 = (uint32_t)__cvta_generic_to_shared(&SA[0][0][0]);
    const uint32_t sb0 = (uint32_t)__cvta_generic_to_shared(&SB[0][0][0]);
    const uint32_t stgB = 128 * RSTR * 4;   // bytes per stage

    // loader: 1024 16B-chunks per operand per stage, 128 threads -> 8 each
    const int lrow = t >> 3;                // 0..15 base row
    const int lseg = t & 7;                 // 16B chunk within 128B row

    float acc[4][8][4];
#pragma unroll
    for (int mt = 0; mt < 4; mt++)
#pragma unroll
        for (int nt = 0; nt < 8; nt++)
#pragma unroll
            for (int r = 0; r < 4; r++) acc[mt][nt][r] = 0.f;

    auto prefetch = [&](int it, int buf) {
        int k0 = it * 32;                   // bf16 elements (32 = 64B... 16 u32)
#pragma unroll
        for (int i = 0; i < 8; i++) {
            int row = lrow + i * 16;        // 0..127
            // each 128B smem row holds BK=32 bf16 * ... : row stride RSTR u32
            // chunk lseg covers u32 [lseg*4, lseg*4+4) -> bf16 [lseg*8, +8)
            // NOTE: BK=32 bf16 = 64B = 4 chunks; use lseg&3, duplicate guard:
            int c = lseg & 3;
            if (lseg < 4) {
                uint32_t da = sa0 + buf * stgB + (row * RSTR + c * 4) * 4;
                int gm = bm + row;
                cp16(da, A + (size_t)gm * KP + k0 + c * 8, gm < M ? 16 : 0);
            } else {
                uint32_t db = sb0 + buf * stgB + (row * RSTR + c * 4) * 4;
                cp16(db, B + (size_t)(bn + row) * KP + k0 + c * 8, 16);
            }
        }
        asm volatile("cp.async.commit_group;");
    };

    const int nit = KP / 32;                // 48
    prefetch(0, 0);
    prefetch(1, 1);

    for (int it = 0; it < nit; it++) {
        if (it == nit - 1)
            asm volatile("cp.async.wait_group 0;");
        else
            asm volatile("cp.async.wait_group 1;");
        __syncthreads();

        if (it + 2 < nit) prefetch(it + 2, (it + 2) % 3);

        const int cur = it % 3;
        uint32_t abase = sa0 + cur * stgB;
        uint32_t bbase = sb0 + cur * stgB;

#pragma unroll
        for (int ks = 0; ks < 2; ks++) {
            // B fragments: 8 n-tiles via 4 ldmatrix.x4 (2 n-tiles + both
            // k-halves per instruction). lane->matrix: (lane>>3)&1 selects
            // n-tile parity, lane>>4 selects k-half.
            uint32_t bf[8][2];
#pragma unroll
            for (int np = 0; np < 4; np++) {
                int nrow = wn * 64 + np * 16 + ((lane >> 3) & 1) * 8 + (lane & 7);
                int kpo  = ks * 8 + (lane >> 4) * 4;
                uint32_t addr = bbase + (nrow * RSTR + kpo) * 4;
                uint32_t r0, r1, r2, r3;
                asm volatile("ldmatrix.sync.aligned.m8n8.x4.shared.b16 {%0,%1,%2,%3}, [%4];"
                             : "=r"(r0), "=r"(r1), "=r"(r2), "=r"(r3) : "r"(addr));
                bf[np * 2 + 0][0] = r0; bf[np * 2 + 0][1] = r2;   // even n-tile
                bf[np * 2 + 1][0] = r1; bf[np * 2 + 1][1] = r3;   // odd n-tile
            }
#pragma unroll
            for (int mt = 0; mt < 4; mt++) {
                int mrow = wm * 64 + mt * 16 + (lane & 7) + ((lane >> 3) & 1) * 8;
                int kpo  = ks * 8 + (lane >> 4) * 4;
                uint32_t addr = abase + (mrow * RSTR + kpo) * 4;
                uint32_t a0, a1, a2, a3;
                asm volatile("ldmatrix.sync.aligned.m8n8.x4.shared.b16 {%0,%1,%2,%3}, [%4];"
                             : "=r"(a0), "=r"(a1), "=r"(a2), "=r"(a3) : "r"(addr));
#pragma unroll
                for (int nt = 0; nt < 8; nt++) {
                    asm volatile(
                        "mma.sync.aligned.m16n8k16.row.col.f32.bf16.bf16.f32 "
                        "{%0,%1,%2,%3}, {%4,%5,%6,%7}, {%8,%9}, {%0,%1,%2,%3};"
                        : "+f"(acc[mt][nt][0]), "+f"(acc[mt][nt][1]),
                          "+f"(acc[mt][nt][2]), "+f"(acc[mt][nt][3])
                        : "r"(a0), "r"(a1), "r"(a2), "r"(a3),
                          "r"(bf[nt][0]), "r"(bf[nt][1]));
                }
            }
        }
    }

    // epilogue: d0:(g,2tg) d1:(g,2tg+1) d2:(g+8,2tg) d3:(g+8,2tg+1)
#pragma unroll
    for (int mt = 0; mt < 4; mt++) {
#pragma unroll
        for (int nt = 0; nt < 8; nt++) {
            int col = bn + wn * 64 + nt * 8 + tg * 2;
            float bx = 0.f, by = 0.f;
            if (bias) { bx = bias[col]; by = bias[col + 1]; }
            int r0 = bm + wm * 64 + mt * 16 + g;
            if (r0 < M) {
                float2 v = make_float2(acc[mt][nt][0] + bx, acc[mt][nt][1] + by);
                *reinterpret_cast<float2*>(C + (size_t)r0 * ldc + col) = v;
            }
            int r1 = r0 + 8;
            if (r1 < M) {
                float2 v = make_float2(acc[mt][nt][2] + bx, acc[mt][nt][3] + by);
                *reinterpret_cast<float2*>(C + (size_t)r1 * ldc + col) = v;
            }
        }
    }
}

// ---------------------------------------------------------------------------
__global__ __launch_bounds__(512)
void act6_kernel(float* __restrict__ h_arr, float* __restrict__ c_arr, int s)
{
    int n = blockIdx.x;
    int d = threadIdx.x;
    const float* wxp = g_wx + (size_t)(s + n) * 2048;
    float i = fast_sigm(wxp[d]);
    float o = fast_sigm(wxp[512 + d]);
    float u = fast_tanh(wxp[1024 + d]);
    float c = i * u;
    float h = o * fast_tanh(c);
    c_arr[(size_t)(s + n) * HID + d] = c;
    h_arr[(size_t)(s + n) * HID + d] = h;
    __nv_bfloat16 hi, lo;
    split_bf16(h, hi, lo);
    __nv_bfloat16* hb = g_hlb + (size_t)n * KP;
    hb[d] = hi; hb[512 + d] = hi; hb[1024 + d] = lo;
}

__global__ __launch_bounds__(512)
void combine_kernel(float* __restrict__ h_arr, float* __restrict__ c_arr, int s)
{
    int n = blockIdx.x;
    int d = threadIdx.x;
    const float* wxp  = g_wx  + (size_t)(s + n) * 2048;
    const float* ioup = g_iou + (size_t)n * 1536;

    float i = fast_sigm(ioup[d]        + wxp[d]);
    float o = fast_sigm(ioup[512 + d]  + wxp[512 + d]);
    float u = fast_tanh(ioup[1024 + d] + wxp[1024 + d]);
    float wxf = wxp[1536 + d];

    float acc = i * u;
    int cbase = 4 * (s + n) + 1;
#pragma unroll
    for (int j = 0; j < 4; j++) {
        float fj = g_f[((size_t)n * 4 + j) * 512 + d] + wxf;
        acc += fj * c_arr[(size_t)(cbase + j) * HID + d];
    }
    float h = o * fast_tanh(acc);
    c_arr[(size_t)(s + n) * HID + d] = acc;
    h_arr[(size_t)(s + n) * HID + d] = h;
    __nv_bfloat16 hi, lo;
    split_bf16(h, hi, lo);
    __nv_bfloat16* hb = g_hlb + (size_t)n * KP;
    hb[d] = hi; hb[512 + d] = hi; hb[1024 + d] = lo;
}

// ---------------------------------------------------------------------------
extern "C" void kernel_launch(void* const* d_in, const int* in_sizes, int n_in,
                              void* d_out, int out_size)
{
    const float* x      = (const float*)d_in[0];
    const float* W_iou  = (const float*)d_in[2];
    const float* b_iou  = (const float*)d_in[3];
    const float* W_f    = (const float*)d_in[4];
    const float* b_f    = (const float*)d_in[5];
    const float* U_iou  = (const float*)d_in[6];
    const float* U_f    = (const float*)d_in[7];

    float* h_arr = (float*)d_out;
    float* c_arr = (float*)d_out + (size_t)N_NODES * HID;

    float *wx, *iou, *fbuf;
    __nv_bfloat16 *xb, *Wb, *Uib, *Ufb, *hsb, *hlb;
    cudaGetSymbolAddress((void**)&wx,  g_wx);
    cudaGetSymbolAddress((void**)&iou, g_iou);
    cudaGetSymbolAddress((void**)&fbuf,g_f);
    cudaGetSymbolAddress((void**)&xb,  g_xb);
    cudaGetSymbolAddress((void**)&Wb,  g_Wb);
    cudaGetSymbolAddress((void**)&Uib, g_Uib);
    cudaGetSymbolAddress((void**)&Ufb, g_Ufb);
    cudaGetSymbolAddress((void**)&hsb, g_hsb);
    cudaGetSymbolAddress((void**)&hlb, g_hlb);
    float* bias;
    cudaGetSymbolAddress((void**)&bias, g_bias);

    // 1. zero leaf rows of h and c
    {
        float4* h4 = (float4*)(h_arr + (size_t)N_INTERNAL * HID);
        float4* c4 = (float4*)(c_arr + (size_t)N_INTERNAL * HID);
        int cnt = (N_NODES - N_INTERNAL) * HID / 4;
        zero_leaves_kernel<<<(cnt + 255) / 256, 256>>>(h4, c4);
    }

    // 2. split-bf16 conversions (Ufb conversion deferred until after the big
    //    GEMM so the big GEMM is the 5th launch -> ncu captures it)
    conv_x_kernel<<<(N_INTERNAL * 512 + 255) / 256, 256>>>(x);
    conv_w_kernel<<<(2048 * 512 + 255) / 256, 256>>>(W_iou, W_f, b_iou, b_f);
    conv_u_kernel<<<(1536 * 512 + 255) / 256, 256>>>(U_iou, Uib, 1536);

    // 3. big GEMM: wx[5461 x 2048] = x' @ Wb^T + bias     (launch #5)
    {
        dim3 g(2048 / 128, (N_INTERNAL + 127) / 128);
        gemm_bf16_3x<<<g, 128>>>(xb, Wb, wx, 2048, bias, N_INTERNAL, 2048);
    }

    // deferred U_f conversion (first used at level 5's f GEMM)
    conv_u_kernel<<<( 512 * 512 + 255) / 256, 256>>>(U_f, Ufb, 512);

    // 4. level 6: nodes [1365, 5461), pure activation (+ split h emit)
    act6_kernel<<<4096, 512>>>(h_arr, c_arr, 1365);

    // 5. levels 5..0
    for (int l = 5; l >= 0; --l) {
        int M  = 1 << (2 * l);
        int s  = (M - 1) / 3;
        int sp = 4 * s + 1;
        const float* hlev = h_arr + (size_t)sp * HID;

        hsum_conv_kernel<<<(M * 512 + 255) / 256, 256>>>(hlev, M);

        {
            dim3 g(1536 / 128, (M + 127) / 128);
            gemm_bf16_3x<<<g, 128>>>(hsb, Uib, iou, 1536, nullptr, M, 1536);
        }
        {
            int Mf = 4 * M;
            dim3 g(512 / 128, (Mf + 127) / 128);
            gemm_bf16_3x<<<g, 128>>>(hlb, Ufb, fbuf, 512, nullptr, Mf, 512);
        }
        combine_kernel<<<M, 512>>>(h_arr, c_arr, s);
    }
}